// round 8
// baseline (speedup 1.0000x reference)
#include <cuda_runtime.h>
#include <cuda_bf16.h>

// Problem constants (fixed by setup_inputs)
#define BB 32      // batch
#define TT 2048    // timesteps
#define HH 512     // hidden per direction
#define DH 1024    // D*H
#define CC 1024    // input feature size
#define NWARP 128  // fused-pass warps per batch
#define WT (TT / NWARP)  // 16 timesteps per warp
#define NPART 32   // merged partials per batch (one per block)
#define SSTAGES 4  // smem ring stages per warp (1 timestep = 4KB each)
#define PRE 3      // stages kept in flight
#define KSPLIT 8   // qproj K-split (k-slice of 128 per block)

// ---------------- scratch (no runtime allocation allowed) ----------------
__device__ float g_qpart[KSPLIT][BB * DH];         // split-K query partials
__device__ float g_scores[BB * TT];                // raw (pre-softmax) scores
__device__ float g_pm[BB * NPART];                 // per-block running max
__device__ float g_pl[BB * NPART];                 // per-block running sum
__device__ float g_pa[(size_t)BB * NPART * DH];    // per-block weighted accum (4 MB)

// ---------------------------------------------------------------------------
// Kernel A: smem-tiled query projection, many light blocks for latency hiding.
//   qpart[ks][b, d] = sum_{k in 128-slice ks} input[b,k] * Wq[d,k]
// grid (64 d-tiles of 16, KSPLIT=8) = 512 blocks x 128 thr, 24 KB smem
// (~3.5 blocks/SM: cp.async wait of one block overlapped by others' compute).
// Warp computes 4 d's x 32 b (lane = b): per kc one conflict-free LDS.128
// (input) + 4 broadcast LDS.128 (w) + 16 FFMA.
// ---------------------------------------------------------------------------
__global__ __launch_bounds__(128) void qproj_kernel(
    const float* __restrict__ input, const float* __restrict__ Wq) {
  const int tid = threadIdx.x;
  const int warp = tid >> 5;
  const int lane = tid & 31;            // lane = b
  const int dt = blockIdx.x;            // d-tile (16 d's)
  const int ks = blockIdx.y;            // k-slice (128 k's)
  const int kbase = ks * (CC / KSPLIT);

  extern __shared__ float4 smq[];       // [0,1024): sIn, [1024,1536): sW
  float4* sIn = smq;                    // sIn[kc*32 + b], kc in [0,32)
  float4* sW = smq + 1024;              // sW[dl*32 + kc], dl in [0,16)

  // stage input slice: 1024 float4 (16 KB), coalesced along kc
#pragma unroll
  for (int i = 0; i < 8; ++i) {
    const int idx = i * 128 + tid;      // (b, kc), kc fast
    const int b = idx >> 5, kc = idx & 31;
    const float* src = input + (size_t)b * CC + kbase + kc * 4;
    unsigned dst = (unsigned)__cvta_generic_to_shared(sIn + kc * 32 + b);
    asm volatile("cp.async.cg.shared.global [%0], [%1], 16;" ::"r"(dst),
                 "l"(src));
  }
  // stage Wq tile: 512 float4 (8 KB), coalesced along kc
#pragma unroll
  for (int i = 0; i < 4; ++i) {
    const int idx = i * 128 + tid;      // (dl, kc), kc fast
    const int dl = idx >> 5, kc = idx & 31;
    const float* src = Wq + (size_t)(dt * 16 + dl) * CC + kbase + kc * 4;
    unsigned dst = (unsigned)__cvta_generic_to_shared(sW + dl * 32 + kc);
    asm volatile("cp.async.cg.shared.global [%0], [%1], 16;" ::"r"(dst),
                 "l"(src));
  }
  asm volatile("cp.async.commit_group;");
  asm volatile("cp.async.wait_group 0;");
  __syncthreads();

  // warp computes d = dt*16 + warp*4 .. +4 for b = lane
  float4 av0 = make_float4(0.f, 0.f, 0.f, 0.f);
  float4 av1 = make_float4(0.f, 0.f, 0.f, 0.f);
  float4 av2 = make_float4(0.f, 0.f, 0.f, 0.f);
  float4 av3 = make_float4(0.f, 0.f, 0.f, 0.f);
  const float4* wrow = sW + warp * 4 * 32;

#pragma unroll 8
  for (int kc = 0; kc < 32; ++kc) {
    const float4 in4 = sIn[kc * 32 + lane];
    const float4 w0 = wrow[kc];
    const float4 w1 = wrow[32 + kc];
    const float4 w2 = wrow[64 + kc];
    const float4 w3 = wrow[96 + kc];
    av0.x = fmaf(w0.x, in4.x, av0.x); av0.y = fmaf(w0.y, in4.y, av0.y);
    av0.z = fmaf(w0.z, in4.z, av0.z); av0.w = fmaf(w0.w, in4.w, av0.w);
    av1.x = fmaf(w1.x, in4.x, av1.x); av1.y = fmaf(w1.y, in4.y, av1.y);
    av1.z = fmaf(w1.z, in4.z, av1.z); av1.w = fmaf(w1.w, in4.w, av1.w);
    av2.x = fmaf(w2.x, in4.x, av2.x); av2.y = fmaf(w2.y, in4.y, av2.y);
    av2.z = fmaf(w2.z, in4.z, av2.z); av2.w = fmaf(w2.w, in4.w, av2.w);
    av3.x = fmaf(w3.x, in4.x, av3.x); av3.y = fmaf(w3.y, in4.y, av3.y);
    av3.z = fmaf(w3.z, in4.z, av3.z); av3.w = fmaf(w3.w, in4.w, av3.w);
  }

  float4 q;
  q.x = (av0.x + av0.y) + (av0.z + av0.w);
  q.y = (av1.x + av1.y) + (av1.z + av1.w);
  q.z = (av2.x + av2.y) + (av2.z + av2.w);
  q.w = (av3.x + av3.y) + (av3.z + av3.w);
  *(float4*)(&g_qpart[ks][lane * DH + dt * 16 + warp * 4]) = q;
}

// ---------------------------------------------------------------------------
// Kernel B: warp-autonomous fused scores + online softmax, cp.async pipeline,
// block-level partial merge at the end (4 warps -> 1 partial per block).
// grid (NWARP/4, BB), 128 threads. Warp owns WT=16 timesteps.
// enc_h layout (D, T, B, H): keys[b,t,dir*H+h] = enc_h[((dir*T+t)*B+b)*H+h]
// ---------------------------------------------------------------------------
__global__ __launch_bounds__(128, 3) void attn_main_kernel(
    const float* __restrict__ enc_h, const float* __restrict__ bq) {
  const int b = blockIdx.y;
  const int warp = threadIdx.x >> 5;
  const int lane = threadIdx.x & 31;
  const int widx = blockIdx.x * 4 + warp;   // 0..NWARP-1 within this batch
  const int t0 = widx * WT;

  const float scale = 0.04419417382415922f;  // 1/sqrt(512)

  extern __shared__ float4 ring[];           // [4 warps][SSTAGES][256] = 64KB
  float4* ringw = ring + warp * (SSTAGES * 256);

  const size_t tstride = (size_t)BB * HH;          // floats per timestep
  const size_t dirstride = (size_t)TT * BB * HH;   // floats per direction
  const float* base0 = enc_h + ((size_t)t0 * BB + b) * HH + lane * 4;
  const float* base1 = base0 + dirstride;

#define LOAD_STAGE(T)                                                        \
  {                                                                          \
    const int slot_ = (T) & (SSTAGES - 1);                                   \
    const float* r0_ = base0 + (size_t)(T)*tstride;                          \
    const float* r1_ = base1 + (size_t)(T)*tstride;                          \
    float4* d_ = ringw + slot_ * 256 + lane;                                 \
    _Pragma("unroll") for (int p = 0; p < 4; ++p) {                          \
      unsigned sa_ = (unsigned)__cvta_generic_to_shared(d_ + p * 32);        \
      asm volatile("cp.async.cg.shared.global [%0], [%1], 16;" ::"r"(sa_),   \
                   "l"(r0_ + p * 128));                                      \
    }                                                                        \
    _Pragma("unroll") for (int p = 0; p < 4; ++p) {                          \
      unsigned sa_ = (unsigned)__cvta_generic_to_shared(d_ + 128 + p * 32);  \
      asm volatile("cp.async.cg.shared.global [%0], [%1], 16;" ::"r"(sa_),   \
                   "l"(r1_ + p * 128));                                      \
    }                                                                        \
  }

  // prologue FIRST: stages 0..PRE-1 in flight before any q work
#pragma unroll
  for (int i = 0; i < PRE; ++i) {
    LOAD_STAGE(i)
    asm volatile("cp.async.commit_group;");
  }

  // q for this lane: q[p] covers d = p*128 + lane*4 (hidden under stage 0)
  float4 q[8];
#pragma unroll
  for (int p = 0; p < 8; ++p) {
    const int d = p * 128 + lane * 4;
    const float4 bb = *(const float4*)(bq + d);
    float4 acc = bb;
#pragma unroll
    for (int ks = 0; ks < KSPLIT; ++ks) {
      const float4 pp = *(const float4*)(&g_qpart[ks][b * DH + d]);
      acc.x += pp.x; acc.y += pp.y; acc.z += pp.z; acc.w += pp.w;
    }
    q[p] = acc;
  }

  float4 a[8];
#pragma unroll
  for (int p = 0; p < 8; ++p) a[p] = make_float4(0.f, 0.f, 0.f, 0.f);
  float m = -1e30f, l = 0.f;

#pragma unroll
  for (int i = 0; i < WT; ++i) {
    if (i + PRE < WT) LOAD_STAGE(i + PRE)
    asm volatile("cp.async.commit_group;");  // empty group ok in tail
    asm volatile("cp.async.wait_group %0;" ::"n"(PRE));  // stage i ready

    const float4* kp = ringw + (i & (SSTAGES - 1)) * 256 + lane;
    float4 k[8];
#pragma unroll
    for (int p = 0; p < 8; ++p) k[p] = kp[p * 32];

    float s = 0.f;
#pragma unroll
    for (int p = 0; p < 8; ++p)
      s += q[p].x * k[p].x + q[p].y * k[p].y + q[p].z * k[p].z +
           q[p].w * k[p].w;
#pragma unroll
    for (int off = 16; off >= 1; off >>= 1)
      s += __shfl_xor_sync(0xffffffffu, s, off);
    s *= scale;

    if (lane == 0) g_scores[b * TT + t0 + i] = s;

    if (s > m) {  // warp-uniform branch (s identical on all lanes)
      const float r = __expf(m - s);
#pragma unroll
      for (int p = 0; p < 8; ++p) {
        a[p].x *= r; a[p].y *= r; a[p].z *= r; a[p].w *= r;
      }
      l *= r;
      m = s;
    }
    const float w = __expf(s - m);
    l += w;
#pragma unroll
    for (int p = 0; p < 8; ++p) {
      a[p].x += w * k[p].x;
      a[p].y += w * k[p].y;
      a[p].z += w * k[p].z;
      a[p].w += w * k[p].w;
    }
  }
#undef LOAD_STAGE

  // ---- block-level merge of the 4 warps' partials (reuse ring smem) ----
  asm volatile("cp.async.wait_group 0;" ::: "memory");

  __shared__ float s_m[4], s_l[4];
  if (lane == 0) { s_m[warp] = m; s_l[warp] = l; }
  __syncthreads();

  const float Mb = fmaxf(fmaxf(s_m[0], s_m[1]), fmaxf(s_m[2], s_m[3]));
  const float Lb = s_l[0] * __expf(s_m[0] - Mb) + s_l[1] * __expf(s_m[1] - Mb) +
                   s_l[2] * __expf(s_m[2] - Mb) + s_l[3] * __expf(s_m[3] - Mb);
  const float wf = __expf(m - Mb);  // warp-uniform rescale factor

  // scaled a -> smem: ring[warp*256 + p*32 + lane] covers d = p*128+lane*4
  float4* mw = ring + warp * 256;
#pragma unroll
  for (int p = 0; p < 8; ++p) {
    float4 v = a[p];
    v.x *= wf; v.y *= wf; v.z *= wf; v.w *= wf;
    mw[p * 32 + lane] = v;
  }
  __syncthreads();

  // cooperative sum of 4 warps' vectors -> one partial per block
  float4* pa4 = (float4*)(g_pa + (size_t)(b * NPART + blockIdx.x) * DH);
#pragma unroll
  for (int r = 0; r < 2; ++r) {
    const int idx = r * 128 + threadIdx.x;  // 0..255 float4s
    const float4 v0 = ring[idx];
    const float4 v1 = ring[256 + idx];
    const float4 v2 = ring[512 + idx];
    const float4 v3 = ring[768 + idx];
    float4 v;
    v.x = v0.x + v1.x + v2.x + v3.x;
    v.y = v0.y + v1.y + v2.y + v3.y;
    v.z = v0.z + v1.z + v2.z + v3.z;
    v.w = v0.w + v1.w + v2.w + v3.w;
    pa4[idx] = v;
  }
  if (threadIdx.x == 0) {
    g_pm[b * NPART + blockIdx.x] = Mb;
    g_pl[b * NPART + blockIdx.x] = Lb;
  }
}

// ---------------------------------------------------------------------------
// Kernel C: combine per-block partials -> attn_values + normalized scores.
// grid (BB, 8), 128 threads: block handles 128 d's + 256 score elements.
// ---------------------------------------------------------------------------
__global__ __launch_bounds__(128) void combine_kernel(float* __restrict__ out) {
  const int b = blockIdx.x;
  const int ds = blockIdx.y;
  const int j = threadIdx.x;

  __shared__ float sm[NPART], sw[NPART];
  __shared__ float sL;
  if (j < NPART) sm[j] = g_pm[b * NPART + j];
  __syncthreads();

  float M = -1e30f;
#pragma unroll
  for (int w = 0; w < NPART; ++w) M = fmaxf(M, sm[w]);
  if (j < NPART) sw[j] = __expf(sm[j] - M);
  __syncthreads();

  if (j == 0) {
    float L = 0.f;
#pragma unroll
    for (int w = 0; w < NPART; ++w) L += g_pl[b * NPART + w] * sw[w];
    sL = 1.f / L;
  }
  __syncthreads();
  const float invL = sL;

  const int d = ds * 128 + j;
  const float* pa = g_pa + (size_t)b * NPART * DH + d;
  float v0 = 0.f, v1 = 0.f, v2 = 0.f, v3 = 0.f;
#pragma unroll
  for (int w = 0; w < NPART; w += 4) {
    v0 += sw[w + 0] * pa[(size_t)(w + 0) * DH];
    v1 += sw[w + 1] * pa[(size_t)(w + 1) * DH];
    v2 += sw[w + 2] * pa[(size_t)(w + 2) * DH];
    v3 += sw[w + 3] * pa[(size_t)(w + 3) * DH];
  }
  out[b * DH + d] = (v0 + v1 + v2 + v3) * invL;

  // fused scores normalization: this block covers t in [ds*256, ds*256+256)
  const int tb = ds * 256 + j * 2;
  const float2 s2 = *(const float2*)(g_scores + b * TT + tb);
  float2 o2;
  o2.x = __expf(s2.x - M) * invL;
  o2.y = __expf(s2.y - M) * invL;
  *(float2*)(out + BB * DH + b * TT + tb) = o2;
}

// ---------------------------------------------------------------------------
extern "C" void kernel_launch(void* const* d_in, const int* in_sizes, int n_in,
                              void* d_out, int out_size) {
  const float* input = (const float*)d_in[0];   // (32, 1024)
  const float* enc_h = (const float*)d_in[1];   // (2, 2048, 32, 512)
  // d_in[2] decoder_state: unused
  const float* Wq = (const float*)d_in[3];      // (1024, 1024)
  const float* bq = (const float*)d_in[4];      // (1024,)
  // d_in[5] t: unused
  float* out = (float*)d_out;  // [attn_values (32*1024)] ++ [attn_scores (32*2048)]

  const int smem_main = 4 * SSTAGES * 256 * sizeof(float4);  // 64 KB
  const int smem_qp = 1536 * sizeof(float4);                 // 24 KB
  cudaFuncSetAttribute(attn_main_kernel,
                       cudaFuncAttributeMaxDynamicSharedMemorySize, smem_main);
  cudaFuncSetAttribute(qproj_kernel,
                       cudaFuncAttributeMaxDynamicSharedMemorySize, smem_qp);

  qproj_kernel<<<dim3(64, KSPLIT), 128, smem_qp>>>(input, Wq);
  attn_main_kernel<<<dim3(NWARP / 4, BB), 128, smem_main>>>(enc_h, bq);
  combine_kernel<<<dim3(BB, 8), 128>>>(out);
}

// round 9
// speedup vs baseline: 1.0676x; 1.0676x over previous
#include <cuda_runtime.h>
#include <cuda_bf16.h>

// Problem constants (fixed by setup_inputs)
#define BB 32      // batch
#define TT 2048    // timesteps
#define HH 512     // hidden per direction
#define DH 1024    // D*H
#define CC 1024    // input feature size
#define NWARP 128  // fused-pass warps per batch
#define WT (TT / NWARP)  // 16 timesteps per warp
#define NPART 32   // merged partials per batch (one per block)
#define SSTAGES 4  // smem ring stages per warp (1 timestep = 4KB each)
#define PRE 3      // stages kept in flight
#define KSPLIT 4   // qproj K-split (k-slice of 256 per block)

// ---------------- scratch (no runtime allocation allowed) ----------------
__device__ float g_qpart[KSPLIT][BB * DH];         // split-K query partials
__device__ float g_scores[BB * TT];                // raw (pre-softmax) scores
__device__ float g_pm[BB * NPART];                 // per-block running max
__device__ float g_pl[BB * NPART];                 // per-block running sum
__device__ float g_pa[(size_t)BB * NPART * DH];    // per-block weighted accum (4 MB)

// ---------------------------------------------------------------------------
// Kernel A: smem-tiled, internally PIPELINED query projection.
//   qpart[ks][b, d] = sum_{k in 256-slice ks} input[b,k] * Wq[d,k]
// grid (32 d-tiles, KSPLIT=4) x 256 thr, 64 KB smem in 4 quarter-stages.
// All 4 quarters are cp.async'd up front (64 KB in flight per block), then
// compute of quarter q overlaps the arrival of quarters q+1..3.
// launch_bounds(256,2) -> <=128 regs so ptxas can hoist next-iter LDS.
// Warp computes 4 d's x 32 b (lane = b).
// ---------------------------------------------------------------------------
__global__ __launch_bounds__(256, 2) void qproj_kernel(
    const float* __restrict__ input, const float* __restrict__ Wq) {
  const int tid = threadIdx.x;
  const int warp = tid >> 5;
  const int lane = tid & 31;            // lane = b
  const int dt = blockIdx.x;            // d-tile (32 d's)
  const int ks = blockIdx.y;            // k-slice (256 k's)
  const int kbase = ks * (CC / KSPLIT);

  // smem: quarter q at smq + q*1024: [0,512) sIn (kc16 x b32), [512,1024) sW
  extern __shared__ float4 smq[];

  // prologue: stage ALL four quarters, one commit group each
#pragma unroll
  for (int qq = 0; qq < 4; ++qq) {
    float4* sInQ = smq + qq * 1024;
    float4* sWQ = sInQ + 512;
    const int kq = kbase + qq * 64;  // quarter covers k in [kq, kq+64)
#pragma unroll
    for (int i = 0; i < 2; ++i) {
      const int idx = i * 256 + tid;   // (b, kc), kc fast (16 per b)
      const int b = idx >> 4, kc = idx & 15;
      const float* src = input + (size_t)b * CC + kq + kc * 4;
      unsigned dst = (unsigned)__cvta_generic_to_shared(sInQ + kc * 32 + b);
      asm volatile("cp.async.cg.shared.global [%0], [%1], 16;" ::"r"(dst),
                   "l"(src));
    }
#pragma unroll
    for (int i = 0; i < 2; ++i) {
      const int idx = i * 256 + tid;   // (dl, kc), kc fast (16 per dl)
      const int dl = idx >> 4, kc = idx & 15;
      const float* src = Wq + (size_t)(dt * 32 + dl) * CC + kq + kc * 4;
      unsigned dst = (unsigned)__cvta_generic_to_shared(sWQ + dl * 16 + kc);
      asm volatile("cp.async.cg.shared.global [%0], [%1], 16;" ::"r"(dst),
                   "l"(src));
    }
    asm volatile("cp.async.commit_group;");
  }

  // warp computes d = dt*32 + warp*4 .. +4 for b = lane
  float4 av0 = make_float4(0.f, 0.f, 0.f, 0.f);
  float4 av1 = make_float4(0.f, 0.f, 0.f, 0.f);
  float4 av2 = make_float4(0.f, 0.f, 0.f, 0.f);
  float4 av3 = make_float4(0.f, 0.f, 0.f, 0.f);

#pragma unroll
  for (int qq = 0; qq < 4; ++qq) {
    // wait until quarter qq has landed (3-qq groups may remain outstanding)
    if (qq == 0) asm volatile("cp.async.wait_group 3;");
    if (qq == 1) asm volatile("cp.async.wait_group 2;");
    if (qq == 2) asm volatile("cp.async.wait_group 1;");
    if (qq == 3) asm volatile("cp.async.wait_group 0;");
    __syncthreads();

    const float4* sInQ = smq + qq * 1024;
    const float4* wrow = sInQ + 512 + warp * 4 * 16;

#pragma unroll
    for (int kc = 0; kc < 16; ++kc) {
      const float4 in4 = sInQ[kc * 32 + lane];
      const float4 w0 = wrow[kc];
      const float4 w1 = wrow[16 + kc];
      const float4 w2 = wrow[32 + kc];
      const float4 w3 = wrow[48 + kc];
      av0.x = fmaf(w0.x, in4.x, av0.x); av0.y = fmaf(w0.y, in4.y, av0.y);
      av0.z = fmaf(w0.z, in4.z, av0.z); av0.w = fmaf(w0.w, in4.w, av0.w);
      av1.x = fmaf(w1.x, in4.x, av1.x); av1.y = fmaf(w1.y, in4.y, av1.y);
      av1.z = fmaf(w1.z, in4.z, av1.z); av1.w = fmaf(w1.w, in4.w, av1.w);
      av2.x = fmaf(w2.x, in4.x, av2.x); av2.y = fmaf(w2.y, in4.y, av2.y);
      av2.z = fmaf(w2.z, in4.z, av2.z); av2.w = fmaf(w2.w, in4.w, av2.w);
      av3.x = fmaf(w3.x, in4.x, av3.x); av3.y = fmaf(w3.y, in4.y, av3.y);
      av3.z = fmaf(w3.z, in4.z, av3.z); av3.w = fmaf(w3.w, in4.w, av3.w);
    }
  }

  float4 q;
  q.x = (av0.x + av0.y) + (av0.z + av0.w);
  q.y = (av1.x + av1.y) + (av1.z + av1.w);
  q.z = (av2.x + av2.y) + (av2.z + av2.w);
  q.w = (av3.x + av3.y) + (av3.z + av3.w);
  *(float4*)(&g_qpart[ks][lane * DH + dt * 32 + warp * 4]) = q;
}

// ---------------------------------------------------------------------------
// Kernel B: warp-autonomous fused scores + online softmax, cp.async pipeline,
// block-level partial merge at the end (4 warps -> 1 partial per block).
// grid (NWARP/4, BB), 128 threads. Warp owns WT=16 timesteps.
// enc_h layout (D, T, B, H): keys[b,t,dir*H+h] = enc_h[((dir*T+t)*B+b)*H+h]
// ---------------------------------------------------------------------------
__global__ __launch_bounds__(128, 3) void attn_main_kernel(
    const float* __restrict__ enc_h, const float* __restrict__ bq) {
  const int b = blockIdx.y;
  const int warp = threadIdx.x >> 5;
  const int lane = threadIdx.x & 31;
  const int widx = blockIdx.x * 4 + warp;   // 0..NWARP-1 within this batch
  const int t0 = widx * WT;

  const float scale = 0.04419417382415922f;  // 1/sqrt(512)

  extern __shared__ float4 ring[];           // [4 warps][SSTAGES][256] = 64KB
  float4* ringw = ring + warp * (SSTAGES * 256);

  const size_t tstride = (size_t)BB * HH;          // floats per timestep
  const size_t dirstride = (size_t)TT * BB * HH;   // floats per direction
  const float* base0 = enc_h + ((size_t)t0 * BB + b) * HH + lane * 4;
  const float* base1 = base0 + dirstride;

#define LOAD_STAGE(T)                                                        \
  {                                                                          \
    const int slot_ = (T) & (SSTAGES - 1);                                   \
    const float* r0_ = base0 + (size_t)(T)*tstride;                          \
    const float* r1_ = base1 + (size_t)(T)*tstride;                          \
    float4* d_ = ringw + slot_ * 256 + lane;                                 \
    _Pragma("unroll") for (int p = 0; p < 4; ++p) {                          \
      unsigned sa_ = (unsigned)__cvta_generic_to_shared(d_ + p * 32);        \
      asm volatile("cp.async.cg.shared.global [%0], [%1], 16;" ::"r"(sa_),   \
                   "l"(r0_ + p * 128));                                      \
    }                                                                        \
    _Pragma("unroll") for (int p = 0; p < 4; ++p) {                          \
      unsigned sa_ = (unsigned)__cvta_generic_to_shared(d_ + 128 + p * 32);  \
      asm volatile("cp.async.cg.shared.global [%0], [%1], 16;" ::"r"(sa_),   \
                   "l"(r1_ + p * 128));                                      \
    }                                                                        \
  }

  // prologue FIRST: stages 0..PRE-1 in flight before any q work
#pragma unroll
  for (int i = 0; i < PRE; ++i) {
    LOAD_STAGE(i)
    asm volatile("cp.async.commit_group;");
  }

  // q for this lane: q[p] covers d = p*128 + lane*4 (hidden under stage 0)
  float4 q[8];
#pragma unroll
  for (int p = 0; p < 8; ++p) {
    const int d = p * 128 + lane * 4;
    const float4 bb = *(const float4*)(bq + d);
    float4 acc = bb;
#pragma unroll
    for (int ks = 0; ks < KSPLIT; ++ks) {
      const float4 pp = *(const float4*)(&g_qpart[ks][b * DH + d]);
      acc.x += pp.x; acc.y += pp.y; acc.z += pp.z; acc.w += pp.w;
    }
    q[p] = acc;
  }

  float4 a[8];
#pragma unroll
  for (int p = 0; p < 8; ++p) a[p] = make_float4(0.f, 0.f, 0.f, 0.f);
  float m = -1e30f, l = 0.f;

#pragma unroll
  for (int i = 0; i < WT; ++i) {
    if (i + PRE < WT) LOAD_STAGE(i + PRE)
    asm volatile("cp.async.commit_group;");  // empty group ok in tail
    asm volatile("cp.async.wait_group %0;" ::"n"(PRE));  // stage i ready

    const float4* kp = ringw + (i & (SSTAGES - 1)) * 256 + lane;
    float4 k[8];
#pragma unroll
    for (int p = 0; p < 8; ++p) k[p] = kp[p * 32];

    float s = 0.f;
#pragma unroll
    for (int p = 0; p < 8; ++p)
      s += q[p].x * k[p].x + q[p].y * k[p].y + q[p].z * k[p].z +
           q[p].w * k[p].w;
#pragma unroll
    for (int off = 16; off >= 1; off >>= 1)
      s += __shfl_xor_sync(0xffffffffu, s, off);
    s *= scale;

    if (lane == 0) g_scores[b * TT + t0 + i] = s;

    if (s > m) {  // warp-uniform branch (s identical on all lanes)
      const float r = __expf(m - s);
#pragma unroll
      for (int p = 0; p < 8; ++p) {
        a[p].x *= r; a[p].y *= r; a[p].z *= r; a[p].w *= r;
      }
      l *= r;
      m = s;
    }
    const float w = __expf(s - m);
    l += w;
#pragma unroll
    for (int p = 0; p < 8; ++p) {
      a[p].x += w * k[p].x;
      a[p].y += w * k[p].y;
      a[p].z += w * k[p].z;
      a[p].w += w * k[p].w;
    }
  }
#undef LOAD_STAGE

  // ---- block-level merge of the 4 warps' partials (reuse ring smem) ----
  asm volatile("cp.async.wait_group 0;" ::: "memory");

  __shared__ float s_m[4], s_l[4];
  if (lane == 0) { s_m[warp] = m; s_l[warp] = l; }
  __syncthreads();

  const float Mb = fmaxf(fmaxf(s_m[0], s_m[1]), fmaxf(s_m[2], s_m[3]));
  const float Lb = s_l[0] * __expf(s_m[0] - Mb) + s_l[1] * __expf(s_m[1] - Mb) +
                   s_l[2] * __expf(s_m[2] - Mb) + s_l[3] * __expf(s_m[3] - Mb);
  const float wf = __expf(m - Mb);  // warp-uniform rescale factor

  // scaled a -> smem: ring[warp*256 + p*32 + lane] covers d = p*128+lane*4
  float4* mw = ring + warp * 256;
#pragma unroll
  for (int p = 0; p < 8; ++p) {
    float4 v = a[p];
    v.x *= wf; v.y *= wf; v.z *= wf; v.w *= wf;
    mw[p * 32 + lane] = v;
  }
  __syncthreads();

  // cooperative sum of 4 warps' vectors -> one partial per block
  float4* pa4 = (float4*)(g_pa + (size_t)(b * NPART + blockIdx.x) * DH);
#pragma unroll
  for (int r = 0; r < 2; ++r) {
    const int idx = r * 128 + threadIdx.x;  // 0..255 float4s
    const float4 v0 = ring[idx];
    const float4 v1 = ring[256 + idx];
    const float4 v2 = ring[512 + idx];
    const float4 v3 = ring[768 + idx];
    float4 v;
    v.x = v0.x + v1.x + v2.x + v3.x;
    v.y = v0.y + v1.y + v2.y + v3.y;
    v.z = v0.z + v1.z + v2.z + v3.z;
    v.w = v0.w + v1.w + v2.w + v3.w;
    pa4[idx] = v;
  }
  if (threadIdx.x == 0) {
    g_pm[b * NPART + blockIdx.x] = Mb;
    g_pl[b * NPART + blockIdx.x] = Lb;
  }
}

// ---------------------------------------------------------------------------
// Kernel C: combine per-block partials -> attn_values + normalized scores.
// grid (BB, 8), 128 threads: block handles 128 d's + 256 score elements.
// ---------------------------------------------------------------------------
__global__ __launch_bounds__(128) void combine_kernel(float* __restrict__ out) {
  const int b = blockIdx.x;
  const int ds = blockIdx.y;
  const int j = threadIdx.x;

  __shared__ float sm[NPART], sw[NPART];
  __shared__ float sL;
  if (j < NPART) sm[j] = g_pm[b * NPART + j];
  __syncthreads();

  float M = -1e30f;
#pragma unroll
  for (int w = 0; w < NPART; ++w) M = fmaxf(M, sm[w]);
  if (j < NPART) sw[j] = __expf(sm[j] - M);
  __syncthreads();

  if (j == 0) {
    float L = 0.f;
#pragma unroll
    for (int w = 0; w < NPART; ++w) L += g_pl[b * NPART + w] * sw[w];
    sL = 1.f / L;
  }
  __syncthreads();
  const float invL = sL;

  const int d = ds * 128 + j;
  const float* pa = g_pa + (size_t)b * NPART * DH + d;
  float v0 = 0.f, v1 = 0.f, v2 = 0.f, v3 = 0.f;
#pragma unroll
  for (int w = 0; w < NPART; w += 4) {
    v0 += sw[w + 0] * pa[(size_t)(w + 0) * DH];
    v1 += sw[w + 1] * pa[(size_t)(w + 1) * DH];
    v2 += sw[w + 2] * pa[(size_t)(w + 2) * DH];
    v3 += sw[w + 3] * pa[(size_t)(w + 3) * DH];
  }
  out[b * DH + d] = (v0 + v1 + v2 + v3) * invL;

  // fused scores normalization: this block covers t in [ds*256, ds*256+256)
  const int tb = ds * 256 + j * 2;
  const float2 s2 = *(const float2*)(g_scores + b * TT + tb);
  float2 o2;
  o2.x = __expf(s2.x - M) * invL;
  o2.y = __expf(s2.y - M) * invL;
  *(float2*)(out + BB * DH + b * TT + tb) = o2;
}

// ---------------------------------------------------------------------------
extern "C" void kernel_launch(void* const* d_in, const int* in_sizes, int n_in,
                              void* d_out, int out_size) {
  const float* input = (const float*)d_in[0];   // (32, 1024)
  const float* enc_h = (const float*)d_in[1];   // (2, 2048, 32, 512)
  // d_in[2] decoder_state: unused
  const float* Wq = (const float*)d_in[3];      // (1024, 1024)
  const float* bq = (const float*)d_in[4];      // (1024,)
  // d_in[5] t: unused
  float* out = (float*)d_out;  // [attn_values (32*1024)] ++ [attn_scores (32*2048)]

  const int smem_main = 4 * SSTAGES * 256 * sizeof(float4);  // 64 KB
  const int smem_qp = 4096 * sizeof(float4);                 // 64 KB
  cudaFuncSetAttribute(attn_main_kernel,
                       cudaFuncAttributeMaxDynamicSharedMemorySize, smem_main);
  cudaFuncSetAttribute(qproj_kernel,
                       cudaFuncAttributeMaxDynamicSharedMemorySize, smem_qp);

  qproj_kernel<<<dim3(32, KSPLIT), 256, smem_qp>>>(input, Wq);
  attn_main_kernel<<<dim3(NWARP / 4, BB), 128, smem_main>>>(enc_h, bq);
  combine_kernel<<<dim3(BB, 8), 128>>>(out);
}